// round 12
// baseline (speedup 1.0000x reference)
#include <cuda_runtime.h>
#include <math.h>

#define BATCH   4096
#define HIDDEN  4096
#define LATENT  20480
#define TAILC   128     // cond(64) + t_embed(64)
#define KIN     (LATENT + TAILC)   // 20608

// Scratch (allocation-free rule: __device__ globals)
__device__ __align__(16) float g_tail[BATCH * TAILC];
__device__ __align__(16) float g_a0[(size_t)BATCH * HIDDEN];
__device__ __align__(16) float g_a1[(size_t)BATCH * HIDDEN];

// ---------------------------------------------------------------------------
// Prep: time features -> 2-layer time MLP -> tail[:,64:128];
//       digit embedding lookup        -> tail[:,0:64]
// One block (64 threads) per batch row.
// ---------------------------------------------------------------------------
__global__ void prep_kernel(const int* __restrict__ timesteps,
                            const int* __restrict__ digits,
                            const int* __restrict__ num_steps,
                            const float* __restrict__ emb,
                            const float* __restrict__ tw0,
                            const float* __restrict__ tb0,
                            const float* __restrict__ tw1,
                            const float* __restrict__ tb1) {
    __shared__ float h[64];
    const int b = blockIdx.x;
    const int i = threadIdx.x;

    const float denom = fmaxf((float)(num_steps[0] - 1), 1.0f);
    const float t = (float)timesteps[b] / denom;
    const float PI = 3.14159265358979323846f;

    float acc = tb0[i]
              + tw0[i * 4 + 0] * t
              + tw0[i * 4 + 1] * (t * t)
              + tw0[i * 4 + 2] * sinf(PI * t)
              + tw0[i * 4 + 3] * cosf(PI * t);
    h[i] = fmaxf(acc, 0.0f);
    __syncthreads();

    float acc2 = tb1[i];
#pragma unroll
    for (int k = 0; k < 64; k++) acc2 += tw1[i * 64 + k] * h[k];

    g_tail[b * TAILC + 64 + i] = acc2;                 // t_embed
    g_tail[b * TAILC + i]      = emb[digits[b] * 64 + i];  // cond
}

// ---------------------------------------------------------------------------
// Tiled fp32 SGEMM:  C[M,N] = act( A[M,K] * W[N,K]^T + bias[N] )
// BM=BN=128, BK=16, 256 threads, 8x8 per-thread tile, double-buffered smem.
// SPLIT: columns >= K0 of A come from A2 (row stride TAILC).
// ---------------------------------------------------------------------------
template<bool RELU, bool SPLIT>
__global__ __launch_bounds__(256, 2)
void gemm_kernel(const float* __restrict__ A,
                 const float* __restrict__ A2,
                 const float* __restrict__ W,
                 const float* __restrict__ bias,
                 float* __restrict__ C,
                 int M, int N, int K, int LDA, int K0) {
    constexpr int BM = 128, BN = 128, BK = 16, PAD = 4;
    __shared__ __align__(16) float As[2][BK][BM + PAD];
    __shared__ __align__(16) float Bs[2][BK][BN + PAD];

    // CTA swizzle (square-ish waves for L2 reuse)
    const int grid_m = M / BM;
    const int grid_n = N / BN;
    const int GROUP  = 16;
    const int pid    = blockIdx.x;
    const int width  = GROUP * grid_n;
    const int group  = pid / width;
    const int first_m = group * GROUP;
    const int gsz     = min(grid_m - first_m, GROUP);
    const int mt = first_m + (pid % gsz);
    const int nt = (pid % width) / gsz;
    const int m0 = mt * BM;
    const int n0 = nt * BN;

    const int tid = threadIdx.x;
    const int tx  = tid & 15;   // output col group
    const int ty  = tid >> 4;   // output row group
    const int lr  = tid >> 2;   // loader row 0..63
    const int lq  = tid & 3;    // loader quad 0..3 (float4)

    float acc[8][8];
#pragma unroll
    for (int i = 0; i < 8; i++)
#pragma unroll
        for (int j = 0; j < 8; j++) acc[i][j] = 0.0f;

    float4 ra0, ra1, rb0, rb1;

    const int nch = K / BK;

    auto LOAD = [&](int c) {
        const int kc = c * BK;
        const float* Ab;
        int lda;
        if (SPLIT && kc >= K0) { Ab = A2 + (kc - K0); lda = TAILC; }
        else                   { Ab = A + kc;         lda = LDA;   }
        ra0 = *reinterpret_cast<const float4*>(Ab + (size_t)(m0 + lr)      * lda + lq * 4);
        ra1 = *reinterpret_cast<const float4*>(Ab + (size_t)(m0 + lr + 64) * lda + lq * 4);
        const float* Wb = W + kc;
        rb0 = *reinterpret_cast<const float4*>(Wb + (size_t)(n0 + lr)      * K + lq * 4);
        rb1 = *reinterpret_cast<const float4*>(Wb + (size_t)(n0 + lr + 64) * K + lq * 4);
    };

    auto STORE = [&](int buf) {
        As[buf][lq * 4 + 0][lr]      = ra0.x;
        As[buf][lq * 4 + 1][lr]      = ra0.y;
        As[buf][lq * 4 + 2][lr]      = ra0.z;
        As[buf][lq * 4 + 3][lr]      = ra0.w;
        As[buf][lq * 4 + 0][lr + 64] = ra1.x;
        As[buf][lq * 4 + 1][lr + 64] = ra1.y;
        As[buf][lq * 4 + 2][lr + 64] = ra1.z;
        As[buf][lq * 4 + 3][lr + 64] = ra1.w;
        Bs[buf][lq * 4 + 0][lr]      = rb0.x;
        Bs[buf][lq * 4 + 1][lr]      = rb0.y;
        Bs[buf][lq * 4 + 2][lr]      = rb0.z;
        Bs[buf][lq * 4 + 3][lr]      = rb0.w;
        Bs[buf][lq * 4 + 0][lr + 64] = rb1.x;
        Bs[buf][lq * 4 + 1][lr + 64] = rb1.y;
        Bs[buf][lq * 4 + 2][lr + 64] = rb1.z;
        Bs[buf][lq * 4 + 3][lr + 64] = rb1.w;
    };

    LOAD(0);
    STORE(0);
    __syncthreads();

    for (int c = 0; c < nch; c++) {
        const int buf = c & 1;
        if (c + 1 < nch) LOAD(c + 1);

#pragma unroll
        for (int k = 0; k < BK; k++) {
            float4 a0v = *reinterpret_cast<const float4*>(&As[buf][k][ty * 8]);
            float4 a1v = *reinterpret_cast<const float4*>(&As[buf][k][ty * 8 + 4]);
            float4 b0v = *reinterpret_cast<const float4*>(&Bs[buf][k][tx * 8]);
            float4 b1v = *reinterpret_cast<const float4*>(&Bs[buf][k][tx * 8 + 4]);
            const float af[8] = {a0v.x, a0v.y, a0v.z, a0v.w, a1v.x, a1v.y, a1v.z, a1v.w};
            const float bf[8] = {b0v.x, b0v.y, b0v.z, b0v.w, b1v.x, b1v.y, b1v.z, b1v.w};
#pragma unroll
            for (int i = 0; i < 8; i++)
#pragma unroll
                for (int j = 0; j < 8; j++)
                    acc[i][j] += af[i] * bf[j];
        }

        if (c + 1 < nch) STORE((c + 1) & 1);
        __syncthreads();
    }

    // Epilogue: bias (+ ReLU), vectorized stores
    float bv[8];
#pragma unroll
    for (int j = 0; j < 8; j++) bv[j] = bias[n0 + tx * 8 + j];

#pragma unroll
    for (int i = 0; i < 8; i++) {
        const int m = m0 + ty * 8 + i;
        float v[8];
#pragma unroll
        for (int j = 0; j < 8; j++) {
            float x = acc[i][j] + bv[j];
            if (RELU) x = fmaxf(x, 0.0f);
            v[j] = x;
        }
        float* cp = C + (size_t)m * N + n0 + tx * 8;
        *reinterpret_cast<float4*>(cp)     = make_float4(v[0], v[1], v[2], v[3]);
        *reinterpret_cast<float4*>(cp + 4) = make_float4(v[4], v[5], v[6], v[7]);
    }
}

// ---------------------------------------------------------------------------
// kernel_launch: prep -> GEMM0(relu, split-A) -> GEMM1(relu) -> GEMM2
// ---------------------------------------------------------------------------
extern "C" void kernel_launch(void* const* d_in, const int* in_sizes, int n_in,
                              void* d_out, int out_size) {
    const float* noisy     = (const float*)d_in[0];
    const int*   digits    = (const int*)  d_in[1];
    const int*   timesteps = (const int*)  d_in[2];
    const int*   num_steps = (const int*)  d_in[3];
    const float* emb       = (const float*)d_in[4];
    const float* tw0       = (const float*)d_in[5];
    const float* tb0       = (const float*)d_in[6];
    const float* tw1       = (const float*)d_in[7];
    const float* tb1       = (const float*)d_in[8];
    const float* nw0       = (const float*)d_in[9];
    const float* nb0       = (const float*)d_in[10];
    const float* nw1       = (const float*)d_in[11];
    const float* nb1       = (const float*)d_in[12];
    const float* nw2       = (const float*)d_in[13];
    const float* nb2       = (const float*)d_in[14];
    float* out = (float*)d_out;

    float *tailp, *a0p, *a1p;
    cudaGetSymbolAddress((void**)&tailp, g_tail);
    cudaGetSymbolAddress((void**)&a0p,   g_a0);
    cudaGetSymbolAddress((void**)&a1p,   g_a1);

    prep_kernel<<<BATCH, 64>>>(timesteps, digits, num_steps, emb, tw0, tb0, tw1, tb1);

    // GEMM0: a0 = relu([x|cond|t_embed] @ nw0^T + nb0)   M=4096 N=4096 K=20608
    {
        dim3 grid((BATCH / 128) * (HIDDEN / 128));
        gemm_kernel<true, true><<<grid, 256>>>(
            noisy, tailp, nw0, nb0, a0p,
            BATCH, HIDDEN, KIN, LATENT, LATENT);
    }
    // GEMM1: a1 = relu(a0 @ nw1^T + nb1)                 M=4096 N=4096 K=4096
    {
        dim3 grid((BATCH / 128) * (HIDDEN / 128));
        gemm_kernel<true, false><<<grid, 256>>>(
            a0p, nullptr, nw1, nb1, a1p,
            BATCH, HIDDEN, HIDDEN, HIDDEN, HIDDEN);
    }
    // GEMM2: out = a1 @ nw2^T + nb2                      M=4096 N=20480 K=4096
    {
        dim3 grid((BATCH / 128) * (LATENT / 128));
        gemm_kernel<false, false><<<grid, 256>>>(
            a1p, nullptr, nw2, nb2, out,
            BATCH, LATENT, HIDDEN, HIDDEN, HIDDEN);
    }
}

// round 15
// speedup vs baseline: 2.7405x; 2.7405x over previous
#include <cuda_runtime.h>
#include <cuda_bf16.h>
#include <math.h>
#include <stdint.h>

#define BATCH   4096
#define HIDDEN  4096
#define LATENT  20480
#define TAILC   128
#define KIN     (LATENT + TAILC)   // 20608

// Scratch (allocation-free rule: __device__ globals)
__device__ __align__(16) float g_tail[BATCH * TAILC];
__device__ __align__(16) float g_a0[(size_t)BATCH * HIDDEN];
__device__ __align__(16) float g_a1[(size_t)BATCH * HIDDEN];

// ---------------------------------------------------------------------------
// Helpers (baseline ISA only: ldmatrix + mma.sync, both sm_80+)
// ---------------------------------------------------------------------------
__device__ __forceinline__ uint32_t smem_u32(const void* p) {
    uint32_t a;
    asm("{ .reg .u64 t; cvta.to.shared.u64 t, %1; cvt.u32.u64 %0, t; }"
        : "=r"(a) : "l"(p));
    return a;
}

__device__ __forceinline__ void ldsm4(uint32_t* r, uint32_t addr) {
    asm volatile("ldmatrix.sync.aligned.m8n8.x4.shared.b16 {%0,%1,%2,%3}, [%4];"
                 : "=r"(r[0]), "=r"(r[1]), "=r"(r[2]), "=r"(r[3]) : "r"(addr));
}

__device__ __forceinline__ void mma16816(float* d, const uint32_t* a, const uint32_t* b) {
    asm volatile(
        "mma.sync.aligned.m16n8k16.row.col.f32.bf16.bf16.f32 "
        "{%0,%1,%2,%3}, {%4,%5,%6,%7}, {%8,%9}, {%0,%1,%2,%3};"
        : "+f"(d[0]), "+f"(d[1]), "+f"(d[2]), "+f"(d[3])
        : "r"(a[0]), "r"(a[1]), "r"(a[2]), "r"(a[3]), "r"(b[0]), "r"(b[1]));
}

// split fp32x4 into bf16 hi/lo x4 (hi = rn(v), lo = rn(v - hi)), store 8B each
__device__ __forceinline__ void split_store(float4 v, char* hi, char* lo, int off) {
    __nv_bfloat162 h01 = __floats2bfloat162_rn(v.x, v.y);
    __nv_bfloat162 h23 = __floats2bfloat162_rn(v.z, v.w);
    float2 f01 = __bfloat1622float2(h01);
    float2 f23 = __bfloat1622float2(h23);
    __nv_bfloat162 l01 = __floats2bfloat162_rn(v.x - f01.x, v.y - f01.y);
    __nv_bfloat162 l23 = __floats2bfloat162_rn(v.z - f23.x, v.w - f23.y);
    *reinterpret_cast<uint2*>(hi + off) =
        make_uint2(*reinterpret_cast<uint32_t*>(&h01), *reinterpret_cast<uint32_t*>(&h23));
    *reinterpret_cast<uint2*>(lo + off) =
        make_uint2(*reinterpret_cast<uint32_t*>(&l01), *reinterpret_cast<uint32_t*>(&l23));
}

// ---------------------------------------------------------------------------
// Prep: time MLP + digit embedding -> g_tail[B,128]
// ---------------------------------------------------------------------------
__global__ void prep_kernel(const int* __restrict__ timesteps,
                            const int* __restrict__ digits,
                            const int* __restrict__ num_steps,
                            const float* __restrict__ emb,
                            const float* __restrict__ tw0,
                            const float* __restrict__ tb0,
                            const float* __restrict__ tw1,
                            const float* __restrict__ tb1) {
    __shared__ float h[64];
    const int b = blockIdx.x;
    const int i = threadIdx.x;

    const float denom = fmaxf((float)(num_steps[0] - 1), 1.0f);
    const float t = (float)timesteps[b] / denom;
    const float PI = 3.14159265358979323846f;

    float acc = tb0[i]
              + tw0[i * 4 + 0] * t
              + tw0[i * 4 + 1] * (t * t)
              + tw0[i * 4 + 2] * sinf(PI * t)
              + tw0[i * 4 + 3] * cosf(PI * t);
    h[i] = fmaxf(acc, 0.0f);
    __syncthreads();

    float acc2 = tb1[i];
#pragma unroll
    for (int k = 0; k < 64; k++) acc2 += tw1[i * 64 + k] * h[k];

    g_tail[b * TAILC + 64 + i] = acc2;
    g_tail[b * TAILC + i]      = emb[digits[b] * 64 + i];
}

// ---------------------------------------------------------------------------
// HMMA bf16x3 GEMM:  C[M,N] = act( A[M,K](fp32) @ W[N,K](fp32)^T + bias )
// BM=BN=128, BK=64. 8 warps (4x2), warp tile 32x64.
// Smem: bf16 hi/lo tiles, row stride 144B (pad) -> ldmatrix conflict-free.
// ---------------------------------------------------------------------------
#define RSB     144                 // row stride bytes (64 bf16 = 128B + 16 pad)
#define TILE_B  (128 * RSB)         // 18432
#define STAGE_B (4 * TILE_B)        // A_hi, A_lo, B_hi, B_lo = 73728
#define SMEM_B  (2 * STAGE_B)       // 147456

template<bool RELU, bool SPLIT>
__global__ __launch_bounds__(256, 1)
void gemm_hmma(const float* __restrict__ A,
               const float* __restrict__ A2,
               const float* __restrict__ W,
               const float* __restrict__ bias,
               float* __restrict__ C,
               int M, int N, int K, int LDA, int K0) {
    extern __shared__ __align__(16) char sm[];
    __shared__ float s_bias[128];

    // CTA swizzle for L2 reuse
    const int grid_m = M / 128;
    const int grid_n = N / 128;
    const int GROUP  = 16;
    const int pid    = blockIdx.x;
    const int width  = GROUP * grid_n;
    const int group  = pid / width;
    const int first_m = group * GROUP;
    const int gsz     = min(grid_m - first_m, GROUP);
    const int mt = first_m + (pid % gsz);
    const int nt = (pid % width) / gsz;
    const int m0 = mt * 128;
    const int n0 = nt * 128;

    const int tid    = threadIdx.x;
    const int wid    = tid >> 5;
    const int lane   = tid & 31;
    const int warp_m = wid & 3;   // 4 warps along M (32 rows each)
    const int warp_n = wid >> 2;  // 2 warps along N (64 cols each)

    if (tid < 128) s_bias[tid] = bias[n0 + tid];

    const uint32_t smbase = smem_u32(sm);

    // per-lane constant parts of ldmatrix addresses (within a tile region)
    const uint32_t aoff = (uint32_t)(warp_m * 32 + (lane & 15)) * RSB + ((lane >> 4) << 4);
    const uint32_t boff = (uint32_t)(warp_n * 64 + ((lane >> 4) << 3) + (lane & 7)) * RSB
                        + (((lane >> 3) & 1) << 4);

    float acc[2][8][4];
#pragma unroll
    for (int i = 0; i < 2; i++)
#pragma unroll
        for (int j = 0; j < 8; j++)
#pragma unroll
            for (int q = 0; q < 4; q++) acc[i][j][q] = 0.0f;

    const int nch = K / 64;
    float4 ra[8], rb[8];

    // loader index mapping: idx = i*256 + tid; row = idx>>4 (0..127), q = idx&15
    auto LOAD = [&](int c) {
        const int kc = c * 64;
        const float* Ab;
        int lda;
        if (SPLIT && kc >= K0) { Ab = A2 + (kc - K0); lda = TAILC; }
        else                   { Ab = A + kc;         lda = LDA;  }
#pragma unroll
        for (int i = 0; i < 8; i++) {
            const int idx = i * 256 + tid;
            const int row = idx >> 4, q = idx & 15;
            ra[i] = *reinterpret_cast<const float4*>(Ab + (size_t)(m0 + row) * lda + q * 4);
            rb[i] = *reinterpret_cast<const float4*>(W + (size_t)(n0 + row) * K + kc + q * 4);
        }
    };

    auto STORE = [&](int buf) {
        char* sa_hi = sm + buf * STAGE_B;
        char* sa_lo = sa_hi + TILE_B;
        char* sb_hi = sa_hi + 2 * TILE_B;
        char* sb_lo = sa_hi + 3 * TILE_B;
#pragma unroll
        for (int i = 0; i < 8; i++) {
            const int idx = i * 256 + tid;
            const int row = idx >> 4, q = idx & 15;
            const int off = row * RSB + q * 8;
            split_store(ra[i], sa_hi, sa_lo, off);
            split_store(rb[i], sb_hi, sb_lo, off);
        }
    };

    LOAD(0);
    STORE(0);
    __syncthreads();

    for (int c = 0; c < nch; c++) {
        if (c + 1 < nch) LOAD(c + 1);

        const uint32_t stage = smbase + (uint32_t)(c & 1) * STAGE_B;
        const uint32_t sa_hi = stage;
        const uint32_t sa_lo = stage + TILE_B;
        const uint32_t sb_hi = stage + 2 * TILE_B;
        const uint32_t sb_lo = stage + 3 * TILE_B;

#pragma unroll
        for (int ks = 0; ks < 4; ks++) {
            const uint32_t kb = ks * 32;  // 16 bf16 = 32 bytes per k-step
            uint32_t ah[2][4], al[2][4];
#pragma unroll
            for (int mtile = 0; mtile < 2; mtile++) {
                const uint32_t ao = aoff + mtile * (16 * RSB) + kb;
                ldsm4(ah[mtile], sa_hi + ao);
                ldsm4(al[mtile], sa_lo + ao);
            }
#pragma unroll
            for (int p = 0; p < 4; p++) {       // pairs of 8-col n-tiles
                uint32_t bh[4], bl[4];
                const uint32_t bo = boff + p * (16 * RSB) + kb;
                ldsm4(bh, sb_hi + bo);
                ldsm4(bl, sb_lo + bo);
#pragma unroll
                for (int mtile = 0; mtile < 2; mtile++) {
                    mma16816(acc[mtile][p * 2],     ah[mtile], bh);
                    mma16816(acc[mtile][p * 2 + 1], ah[mtile], bh + 2);
                    mma16816(acc[mtile][p * 2],     ah[mtile], bl);
                    mma16816(acc[mtile][p * 2 + 1], ah[mtile], bl + 2);
                    mma16816(acc[mtile][p * 2],     al[mtile], bh);
                    mma16816(acc[mtile][p * 2 + 1], al[mtile], bh + 2);
                }
            }
        }

        if (c + 1 < nch) STORE((c + 1) & 1);
        __syncthreads();
    }

    // Epilogue: c0,c1 -> (row, col..col+1); c2,c3 -> (row+8, col..col+1)
    const int row_b = m0 + warp_m * 32 + (lane >> 2);
    const int col_l = warp_n * 64 + (lane & 3) * 2;   // within 128-col tile
#pragma unroll
    for (int mtile = 0; mtile < 2; mtile++) {
#pragma unroll
        for (int ntile = 0; ntile < 8; ntile++) {
            const int cl = col_l + ntile * 8;
            const float b0 = s_bias[cl], b1 = s_bias[cl + 1];
            float v0 = acc[mtile][ntile][0] + b0;
            float v1 = acc[mtile][ntile][1] + b1;
            float v2 = acc[mtile][ntile][2] + b0;
            float v3 = acc[mtile][ntile][3] + b1;
            if (RELU) {
                v0 = fmaxf(v0, 0.0f); v1 = fmaxf(v1, 0.0f);
                v2 = fmaxf(v2, 0.0f); v3 = fmaxf(v3, 0.0f);
            }
            const int r0 = row_b + mtile * 16;
            float* p0 = C + (size_t)r0 * N + n0 + cl;
            float* p1 = C + (size_t)(r0 + 8) * N + n0 + cl;
            *reinterpret_cast<float2*>(p0) = make_float2(v0, v1);
            *reinterpret_cast<float2*>(p1) = make_float2(v2, v3);
        }
    }
}

// ---------------------------------------------------------------------------
// kernel_launch
// ---------------------------------------------------------------------------
extern "C" void kernel_launch(void* const* d_in, const int* in_sizes, int n_in,
                              void* d_out, int out_size) {
    const float* noisy     = (const float*)d_in[0];
    const int*   digits    = (const int*)  d_in[1];
    const int*   timesteps = (const int*)  d_in[2];
    const int*   num_steps = (const int*)  d_in[3];
    const float* emb       = (const float*)d_in[4];
    const float* tw0       = (const float*)d_in[5];
    const float* tb0       = (const float*)d_in[6];
    const float* tw1       = (const float*)d_in[7];
    const float* tb1       = (const float*)d_in[8];
    const float* nw0       = (const float*)d_in[9];
    const float* nb0       = (const float*)d_in[10];
    const float* nw1       = (const float*)d_in[11];
    const float* nb1       = (const float*)d_in[12];
    const float* nw2       = (const float*)d_in[13];
    const float* nb2       = (const float*)d_in[14];
    float* out = (float*)d_out;

    float *tailp, *a0p, *a1p;
    cudaGetSymbolAddress((void**)&tailp, g_tail);
    cudaGetSymbolAddress((void**)&a0p,   g_a0);
    cudaGetSymbolAddress((void**)&a1p,   g_a1);

    cudaFuncSetAttribute(gemm_hmma<true, true>,
                         cudaFuncAttributeMaxDynamicSharedMemorySize, SMEM_B);
    cudaFuncSetAttribute(gemm_hmma<true, false>,
                         cudaFuncAttributeMaxDynamicSharedMemorySize, SMEM_B);
    cudaFuncSetAttribute(gemm_hmma<false, false>,
                         cudaFuncAttributeMaxDynamicSharedMemorySize, SMEM_B);

    prep_kernel<<<BATCH, 64>>>(timesteps, digits, num_steps, emb, tw0, tb0, tw1, tb1);

    // GEMM0: a0 = relu([x|tail] @ nw0^T + nb0)   M=4096 N=4096 K=20608
    gemm_hmma<true, true><<<(BATCH / 128) * (HIDDEN / 128), 256, SMEM_B>>>(
        noisy, tailp, nw0, nb0, a0p, BATCH, HIDDEN, KIN, LATENT, LATENT);

    // GEMM1: a1 = relu(a0 @ nw1^T + nb1)         M=4096 N=4096 K=4096
    gemm_hmma<true, false><<<(BATCH / 128) * (HIDDEN / 128), 256, SMEM_B>>>(
        a0p, nullptr, nw1, nb1, a1p, BATCH, HIDDEN, HIDDEN, HIDDEN, HIDDEN);

    // GEMM2: out = a1 @ nw2^T + nb2              M=4096 N=20480 K=4096
    gemm_hmma<false, false><<<(BATCH / 128) * (LATENT / 128), 256, SMEM_B>>>(
        a1p, nullptr, nw2, nb2, out, BATCH, LATENT, HIDDEN, HIDDEN, HIDDEN);
}